// round 1
// baseline (speedup 1.0000x reference)
#include <cuda_runtime.h>
#include <math.h>

#define BB 16
#define SS 512
#define DD 1024
#define NTOK (BB*SS)

// ------------------------------ scratch (static device globals; no allocs) --
__device__ float g_q[(size_t)NTOK * DD];     // compacted q rows per batch (cap 512)
__device__ float g_k[(size_t)NTOK * DD];     // compacted k rows per batch
__device__ float g_invn[NTOK];               // 1 / max(||e||, 1e-12)
__device__ int   g_idx0[NTOK];               // compacted i-token indices per batch
__device__ int   g_idx1[NTOK];               // compacted j-token indices per batch
__device__ int   g_cnt[2 * BB];              // [b]=n0, [BB+b]=n1
__device__ float g_pm[BB * 64];              // per-tile softmax partials: max
__device__ float g_pl[BB * 64];              // per-tile partials: sum exp
__device__ float g_pa[BB * 64];              // per-tile partials: sum exp*score

#define NEG_BIG (-3.0e38f)

__device__ __forceinline__ void softmax_merge(float& m1, float& l1, float& a1,
                                              float m2, float l2, float a2) {
    float M  = fmaxf(m1, m2);
    float e1 = (l1 > 0.f) ? expf(m1 - M) : 0.f;
    float e2 = (l2 > 0.f) ? expf(m2 - M) : 0.f;
    l1 = l1 * e1 + l2 * e2;
    a1 = a1 * e1 + a2 * e2;
    m1 = M;
}

// ---------------------------------------------------------- mask compaction --
// One block per batch, 512 threads. Deterministic order via ballot prefix.
__global__ void prep_masks(const int* __restrict__ am, const int* __restrict__ tt) {
    int b = blockIdx.x;
    int t = threadIdx.x;
    int lane = t & 31, w = t >> 5;
    int a  = am[b * SS + t];
    int ty = tt[b * SS + t];
    bool f0 = (a == 1) && (ty == 0);
    bool f1 = (a == 1) && (ty == 1);
    unsigned bal0 = __ballot_sync(0xffffffffu, f0);
    unsigned bal1 = __ballot_sync(0xffffffffu, f1);
    __shared__ int wc0[16], wc1[16], off0[16], off1[16];
    if (lane == 0) { wc0[w] = __popc(bal0); wc1[w] = __popc(bal1); }
    __syncthreads();
    if (t == 0) {
        int s0 = 0, s1 = 0;
        for (int i = 0; i < 16; i++) {
            off0[i] = s0; s0 += wc0[i];
            off1[i] = s1; s1 += wc1[i];
        }
        g_cnt[b] = s0; g_cnt[BB + b] = s1;
    }
    __syncthreads();
    if (f0) g_idx0[b * SS + off0[w] + __popc(bal0 & ((1u << lane) - 1u))] = t;
    if (f1) g_idx1[b * SS + off1[w] + __popc(bal1 & ((1u << lane) - 1u))] = t;
}

// ------------------------------------------------------------- row inv-norms --
__global__ void row_norms(const float* __restrict__ E) {
    int row = blockIdx.x;                    // 0..NTOK-1
    const float4* p = (const float4*)(E + (size_t)row * DD);
    float s = 0.f;
    for (int i = threadIdx.x; i < DD / 4; i += 128) {
        float4 v = p[i];
        s += v.x * v.x + v.y * v.y + v.z * v.z + v.w * v.w;
    }
    #pragma unroll
    for (int o = 16; o > 0; o >>= 1) s += __shfl_down_sync(0xffffffffu, s, o);
    __shared__ float ws[4];
    int lane = threadIdx.x & 31, w = threadIdx.x >> 5;
    if (lane == 0) ws[w] = s;
    __syncthreads();
    if (threadIdx.x == 0) {
        float tot = ws[0] + ws[1] + ws[2] + ws[3];
        g_invn[row] = 1.f / fmaxf(sqrtf(tot), 1e-12f);
    }
}

// --------------------------------------------- gathered projection GEMM (NT) --
// out[(b*SS + r)*DD + c] = sum_k E[b, idx[r], k] * W[c, k] + bias[c], r < cnt[b]
// which: 0 -> (g_idx0, g_cnt[b], g_q), 1 -> (g_idx1, g_cnt[BB+b], g_k)
// BM=BN=128, BK=16, 256 threads, 8x8 microtile.
__global__ __launch_bounds__(256) void proj_gemm(
    const float* __restrict__ E, const float* __restrict__ W,
    const float* __restrict__ bias, int which)
{
    int b  = blockIdx.z;
    int nr = g_cnt[which * BB + b];
    int r0 = blockIdx.y * 128;
    if (r0 >= nr) return;
    int c0 = blockIdx.x * 128;
    const int* __restrict__ idx = which ? g_idx1 : g_idx0;
    float* __restrict__ out     = which ? g_k    : g_q;

    __shared__ float As[16][128];
    __shared__ float Bs[16][128];
    __shared__ int   sidx[128];
    int tid = threadIdx.x;
    if (tid < 128) {
        int r = r0 + tid;
        sidx[tid] = idx[b * SS + min(r, nr - 1)];
    }
    __syncthreads();

    float acc[8][8];
    #pragma unroll
    for (int i = 0; i < 8; i++)
        #pragma unroll
        for (int j = 0; j < 8; j++) acc[i][j] = 0.f;

    const float* Eb = E + (size_t)b * SS * DD;
    int ty = tid >> 4, tx = tid & 15;
    int larow = tid >> 1;            // 0..127
    int lak   = (tid & 1) * 8;       // 0 or 8

    const float* arow = Eb + (size_t)sidx[larow] * DD + lak;
    const float* brow = W + (size_t)(c0 + larow) * DD + lak;

    for (int k0 = 0; k0 < DD; k0 += 16) {
        float4 a0 = *(const float4*)(arow + k0);
        float4 a1 = *(const float4*)(arow + k0 + 4);
        float4 b0 = *(const float4*)(brow + k0);
        float4 b1 = *(const float4*)(brow + k0 + 4);
        As[lak + 0][larow] = a0.x; As[lak + 1][larow] = a0.y;
        As[lak + 2][larow] = a0.z; As[lak + 3][larow] = a0.w;
        As[lak + 4][larow] = a1.x; As[lak + 5][larow] = a1.y;
        As[lak + 6][larow] = a1.z; As[lak + 7][larow] = a1.w;
        Bs[lak + 0][larow] = b0.x; Bs[lak + 1][larow] = b0.y;
        Bs[lak + 2][larow] = b0.z; Bs[lak + 3][larow] = b0.w;
        Bs[lak + 4][larow] = b1.x; Bs[lak + 5][larow] = b1.y;
        Bs[lak + 6][larow] = b1.z; Bs[lak + 7][larow] = b1.w;
        __syncthreads();
        #pragma unroll
        for (int k = 0; k < 16; k++) {
            float av[8], bv[8];
            *(float4*)&av[0] = *(const float4*)&As[k][ty * 8];
            *(float4*)&av[4] = *(const float4*)&As[k][ty * 8 + 4];
            *(float4*)&bv[0] = *(const float4*)&Bs[k][tx * 8];
            *(float4*)&bv[4] = *(const float4*)&Bs[k][tx * 8 + 4];
            #pragma unroll
            for (int i = 0; i < 8; i++)
                #pragma unroll
                for (int j = 0; j < 8; j++)
                    acc[i][j] = fmaf(av[i], bv[j], acc[i][j]);
        }
        __syncthreads();
    }

    #pragma unroll
    for (int i = 0; i < 8; i++) {
        int r = r0 + ty * 8 + i;
        if (r < nr) {
            float* orow = out + ((size_t)b * SS + r) * DD + c0 + tx * 8;
            #pragma unroll
            for (int j = 0; j < 8; j++)
                orow[j] = acc[i][j] + bias[c0 + tx * 8 + j];
        }
    }
}

// ------------------------------------------------- fused pair + online softmax
// 64x64 pair tiles per block, dual accumulators (logit = q.k, gram = e.e).
__global__ __launch_bounds__(256) void pair_kernel(const float* __restrict__ E) {
    int b   = blockIdx.z;
    int pid = blockIdx.y * 8 + blockIdx.x;
    int n0  = g_cnt[b], n1 = g_cnt[BB + b];
    int i0  = blockIdx.y * 64, j0 = blockIdx.x * 64;
    int tid = threadIdx.x;
    if (i0 >= n0 || j0 >= n1) {
        if (tid == 0) {
            g_pm[b * 64 + pid] = NEG_BIG;
            g_pl[b * 64 + pid] = 0.f;
            g_pa[b * 64 + pid] = 0.f;
        }
        return;
    }
    __shared__ float Qs[16][64], Is[16][64], Ks[16][64], Js[16][64];
    __shared__ float sinvi[64], sinvj[64];
    __shared__ int   si[64], sj[64];
    if (tid < 64) {
        int r  = min(i0 + tid, n0 - 1);
        int ix = g_idx0[b * SS + r];
        si[tid] = ix; sinvi[tid] = g_invn[b * SS + ix];
        int c  = min(j0 + tid, n1 - 1);
        int jx = g_idx1[b * SS + c];
        sj[tid] = jx; sinvj[tid] = g_invn[b * SS + jx];
    }
    __syncthreads();

    float accL[4][4], accG[4][4];
    #pragma unroll
    for (int i = 0; i < 4; i++)
        #pragma unroll
        for (int j = 0; j < 4; j++) { accL[i][j] = 0.f; accG[i][j] = 0.f; }

    int row = tid >> 2;          // 0..63 (load row)
    int kk  = (tid & 3) * 4;     // 0,4,8,12
    int iq  = min(i0 + row, n0 - 1);
    int jq  = min(j0 + row, n1 - 1);
    const float* qptr  = g_q + ((size_t)b * SS + iq) * DD + kk;
    const float* kptr  = g_k + ((size_t)b * SS + jq) * DD + kk;
    const float* eiptr = E + ((size_t)b * SS + si[row]) * DD + kk;
    const float* ejptr = E + ((size_t)b * SS + sj[row]) * DD + kk;
    int ty = tid >> 4, tx = tid & 15;

    for (int k0 = 0; k0 < DD; k0 += 16) {
        float4 q4 = *(const float4*)(qptr + k0);
        float4 i4 = *(const float4*)(eiptr + k0);
        float4 k4 = *(const float4*)(kptr + k0);
        float4 j4 = *(const float4*)(ejptr + k0);
        Qs[kk + 0][row] = q4.x; Qs[kk + 1][row] = q4.y; Qs[kk + 2][row] = q4.z; Qs[kk + 3][row] = q4.w;
        Is[kk + 0][row] = i4.x; Is[kk + 1][row] = i4.y; Is[kk + 2][row] = i4.z; Is[kk + 3][row] = i4.w;
        Ks[kk + 0][row] = k4.x; Ks[kk + 1][row] = k4.y; Ks[kk + 2][row] = k4.z; Ks[kk + 3][row] = k4.w;
        Js[kk + 0][row] = j4.x; Js[kk + 1][row] = j4.y; Js[kk + 2][row] = j4.z; Js[kk + 3][row] = j4.w;
        __syncthreads();
        #pragma unroll
        for (int k = 0; k < 16; k++) {
            float qa[4], ia[4], kb[4], jb[4];
            *(float4*)&qa[0] = *(const float4*)&Qs[k][ty * 4];
            *(float4*)&ia[0] = *(const float4*)&Is[k][ty * 4];
            *(float4*)&kb[0] = *(const float4*)&Ks[k][tx * 4];
            *(float4*)&jb[0] = *(const float4*)&Js[k][tx * 4];
            #pragma unroll
            for (int i = 0; i < 4; i++)
                #pragma unroll
                for (int j = 0; j < 4; j++) {
                    accL[i][j] = fmaf(qa[i], kb[j], accL[i][j]);
                    accG[i][j] = fmaf(ia[i], jb[j], accG[i][j]);
                }
        }
        __syncthreads();
    }

    // thread-local online softmax over its 4x4 pairs
    int ri = ty * 4, rj = tx * 4;
    float m = NEG_BIG, l = 0.f, a = 0.f;
    #pragma unroll
    for (int i = 0; i < 4; i++)
        #pragma unroll
        for (int j = 0; j < 4; j++) {
            if (i0 + ri + i < n0 && j0 + rj + j < n1)
                m = fmaxf(m, accL[i][j]);
        }
    if (m > NEG_BIG * 0.5f) {
        #pragma unroll
        for (int i = 0; i < 4; i++)
            #pragma unroll
            for (int j = 0; j < 4; j++) {
                if (i0 + ri + i < n0 && j0 + rj + j < n1) {
                    float w  = expf(accL[i][j] - m);
                    float sc = fabsf(accG[i][j]) * sinvi[ri + i] * sinvj[rj + j];
                    l += w;
                    a += w * sc;
                }
            }
    }

    // block reduce (m, l, a)
    __shared__ float rm_[256], rl_[256], ra_[256];
    rm_[tid] = m; rl_[tid] = l; ra_[tid] = a;
    __syncthreads();
    for (int s = 128; s > 0; s >>= 1) {
        if (tid < s) {
            float M = rm_[tid], L = rl_[tid], A = ra_[tid];
            softmax_merge(M, L, A, rm_[tid + s], rl_[tid + s], ra_[tid + s]);
            rm_[tid] = M; rl_[tid] = L; ra_[tid] = A;
        }
        __syncthreads();
    }
    if (tid == 0) {
        g_pm[b * 64 + pid] = rm_[0];
        g_pl[b * 64 + pid] = rl_[0];
        g_pa[b * 64 + pid] = ra_[0];
    }
}

// ------------------------------------------------------------------ finalize --
__global__ void finalize(float* __restrict__ out) {
    int b = blockIdx.x;
    int t = threadIdx.x;   // 64 threads
    __shared__ float sm[64], sl[64], sa[64];
    sm[t] = g_pm[b * 64 + t];
    sl[t] = g_pl[b * 64 + t];
    sa[t] = g_pa[b * 64 + t];
    __syncthreads();
    for (int s = 32; s > 0; s >>= 1) {
        if (t < s) {
            float M = sm[t], L = sl[t], A = sa[t];
            softmax_merge(M, L, A, sm[t + s], sl[t + s], sa[t + s]);
            sm[t] = M; sl[t] = L; sa[t] = A;
        }
        __syncthreads();
    }
    if (t == 0) out[b] = (sl[0] > 0.f) ? (sa[0] / sl[0]) : 0.f;
}

// -------------------------------------------------------------------- launch --
extern "C" void kernel_launch(void* const* d_in, const int* in_sizes, int n_in,
                              void* d_out, int out_size) {
    const float* E  = (const float*)d_in[0];
    const float* Wq = (const float*)d_in[1];
    const float* bq = (const float*)d_in[2];
    const float* Wk = (const float*)d_in[3];
    const float* bk = (const float*)d_in[4];
    const int*   am = (const int*)d_in[5];
    const int*   tt = (const int*)d_in[6];
    float* out = (float*)d_out;

    prep_masks<<<BB, 512>>>(am, tt);
    row_norms<<<NTOK, 128>>>(E);
    proj_gemm<<<dim3(8, 4, BB), 256>>>(E, Wq, bq, 0);
    proj_gemm<<<dim3(8, 4, BB), 256>>>(E, Wk, bk, 1);
    pair_kernel<<<dim3(8, 8, BB), 256>>>(E);
    finalize<<<BB, 64>>>(out);
}

// round 3
// speedup vs baseline: 1.7377x; 1.7377x over previous
#include <cuda_runtime.h>
#include <cuda_bf16.h>
#include <math.h>
#include <stdint.h>

#define BB 16
#define SS 512
#define DD 1024
#define NTOK (BB*SS)
#define NEG_BIG (-3.0e38f)

// ------------------------------ scratch (static device globals; no allocs) --
__device__ float g_q[(size_t)NTOK * DD];
__device__ float g_k[(size_t)NTOK * DD];
__device__ float g_invn[NTOK];
__device__ int   g_idx0[NTOK];
__device__ int   g_idx1[NTOK];
__device__ int   g_cnt[2 * BB];
__device__ float g_pm[BB * 64];
__device__ float g_pl[BB * 64];
__device__ float g_pa[BB * 64];

__device__ __forceinline__ void softmax_merge(float& m1, float& l1, float& a1,
                                              float m2, float l2, float a2) {
    float M  = fmaxf(m1, m2);
    float e1 = (l1 > 0.f) ? expf(m1 - M) : 0.f;
    float e2 = (l2 > 0.f) ? expf(m2 - M) : 0.f;
    l1 = l1 * e1 + l2 * e2;
    a1 = a1 * e1 + a2 * e2;
    m1 = M;
}

// ---------------------------------------------------------- mask compaction --
__global__ void prep_masks(const int* __restrict__ am, const int* __restrict__ tt) {
    int b = blockIdx.x;
    int t = threadIdx.x;
    int lane = t & 31, w = t >> 5;
    int a  = am[b * SS + t];
    int ty = tt[b * SS + t];
    bool f0 = (a == 1) && (ty == 0);
    bool f1 = (a == 1) && (ty == 1);
    unsigned bal0 = __ballot_sync(0xffffffffu, f0);
    unsigned bal1 = __ballot_sync(0xffffffffu, f1);
    __shared__ int wc0[16], wc1[16], off0[16], off1[16];
    if (lane == 0) { wc0[w] = __popc(bal0); wc1[w] = __popc(bal1); }
    __syncthreads();
    if (t == 0) {
        int s0 = 0, s1 = 0;
        for (int i = 0; i < 16; i++) {
            off0[i] = s0; s0 += wc0[i];
            off1[i] = s1; s1 += wc1[i];
        }
        g_cnt[b] = s0; g_cnt[BB + b] = s1;
    }
    __syncthreads();
    if (f0) g_idx0[b * SS + off0[w] + __popc(bal0 & ((1u << lane) - 1u))] = t;
    if (f1) g_idx1[b * SS + off1[w] + __popc(bal1 & ((1u << lane) - 1u))] = t;
}

// ------------------------------------------------------------- row inv-norms --
__global__ void row_norms(const float* __restrict__ E) {
    int row = blockIdx.x;
    const float4* p = (const float4*)(E + (size_t)row * DD);
    float s = 0.f;
    for (int i = threadIdx.x; i < DD / 4; i += 128) {
        float4 v = p[i];
        s += v.x * v.x + v.y * v.y + v.z * v.z + v.w * v.w;
    }
    #pragma unroll
    for (int o = 16; o > 0; o >>= 1) s += __shfl_down_sync(0xffffffffu, s, o);
    __shared__ float ws[4];
    int lane = threadIdx.x & 31, w = threadIdx.x >> 5;
    if (lane == 0) ws[w] = s;
    __syncthreads();
    if (threadIdx.x == 0) {
        float tot = ws[0] + ws[1] + ws[2] + ws[3];
        g_invn[row] = 1.f / fmaxf(sqrtf(tot), 1e-12f);
    }
}

// ---------------------------------- mma.sync bf16x3 gathered projection GEMM --
// z = batch | (which<<4). D[128x128] = gather(E)[128x1024] @ W[c0:c0+128, :]^T + bias
// bf16 3-product split (hh + hl + lh) for ~fp32 accuracy.
#define BK 32
#define STRA 34          // padded row stride in bf16 elems (kills LDS bank conflicts)

__device__ __forceinline__ uint32_t pack_bf2(float x, float y) {
    __nv_bfloat162 h = __floats2bfloat162_rn(x, y);
    return *(uint32_t*)&h;
}
__device__ __forceinline__ void mma16816(float* c, const uint32_t* a, const uint32_t* b) {
    asm volatile(
        "mma.sync.aligned.m16n8k16.row.col.f32.bf16.bf16.f32 "
        "{%0,%1,%2,%3}, {%4,%5,%6,%7}, {%8,%9}, {%0,%1,%2,%3};"
        : "+f"(c[0]), "+f"(c[1]), "+f"(c[2]), "+f"(c[3])
        : "r"(a[0]), "r"(a[1]), "r"(a[2]), "r"(a[3]), "r"(b[0]), "r"(b[1]));
}

__global__ __launch_bounds__(256) void proj_mma(
    const float* __restrict__ E,
    const float* __restrict__ Wq, const float* __restrict__ bq,
    const float* __restrict__ Wk, const float* __restrict__ bk)
{
    int z = blockIdx.z;
    int b = z & 15, which = z >> 4;
    int nr = g_cnt[which * BB + b];
    int r0 = blockIdx.y * 128;
    if (r0 >= nr) return;
    int c0 = blockIdx.x * 128;
    const float* __restrict__ W    = which ? Wk : Wq;
    const float* __restrict__ bias = which ? bk : bq;
    const int*   __restrict__ idx  = which ? g_idx1 : g_idx0;
    float*       __restrict__ out  = which ? g_k : g_q;

    __shared__ __align__(16) uint16_t Ah[128 * STRA];
    __shared__ __align__(16) uint16_t Al[128 * STRA];
    __shared__ __align__(16) uint16_t Bh[128 * STRA];
    __shared__ __align__(16) uint16_t Bl[128 * STRA];
    __shared__ int sidx[128];

    int t = threadIdx.x;
    if (t < 128) sidx[t] = idx[b * SS + min(r0 + t, nr - 1)];
    __syncthreads();

    // ---- global load plan: each thread owns 4 (row, 128B-seg) units per matrix
    int lrow = t >> 3;           // 0..31
    int seg  = t & 7;            // 0..7 (16B segments of the 128B chunk row)
    const float* Eb = E + (size_t)b * SS * DD;
    const float* ap[4];
    const float* bp[4];
    #pragma unroll
    for (int i = 0; i < 4; i++) {
        int row = lrow + i * 32;
        ap[i] = Eb + (size_t)sidx[row] * DD + seg * 4;
        bp[i] = W + (size_t)(c0 + row) * DD + seg * 4;
    }

    // ---- warp tiling: 8 warps = 2 (rows of 64) x 4 (cols of 32)
    int wid = t >> 5, lane = t & 31;
    int wy = wid >> 2, wx = wid & 3;
    int grp = lane >> 2, qd = lane & 3;

    float acc[4][4][4];
    #pragma unroll
    for (int mt = 0; mt < 4; mt++)
        #pragma unroll
        for (int nt = 0; nt < 4; nt++)
            #pragma unroll
            for (int r = 0; r < 4; r++) acc[mt][nt][r] = 0.f;

    float4 va[4], vb[4];
    #pragma unroll
    for (int i = 0; i < 4; i++) { va[i] = *(const float4*)ap[i]; vb[i] = *(const float4*)bp[i]; }

    for (int c = 0; c < DD / BK; c++) {
        // store current chunk (hi/lo bf16 split) to SMEM
        #pragma unroll
        for (int i = 0; i < 4; i++) {
            int row = lrow + i * 32;
            uint16_t* dA = Ah + row * STRA + seg * 4;
            uint16_t* dAl = Al + row * STRA + seg * 4;
            uint16_t* dB = Bh + row * STRA + seg * 4;
            uint16_t* dBl = Bl + row * STRA + seg * 4;
            float a0 = va[i].x, a1 = va[i].y, a2 = va[i].z, a3 = va[i].w;
            float b0 = vb[i].x, b1 = vb[i].y, b2 = vb[i].z, b3 = vb[i].w;
            uint32_t ah01 = pack_bf2(a0, a1), ah23 = pack_bf2(a2, a3);
            uint32_t bh01 = pack_bf2(b0, b1), bh23 = pack_bf2(b2, b3);
            __nv_bfloat162 ha01 = *(__nv_bfloat162*)&ah01, ha23 = *(__nv_bfloat162*)&ah23;
            __nv_bfloat162 hb01 = *(__nv_bfloat162*)&bh01, hb23 = *(__nv_bfloat162*)&bh23;
            uint32_t al01 = pack_bf2(a0 - __bfloat162float(ha01.x), a1 - __bfloat162float(ha01.y));
            uint32_t al23 = pack_bf2(a2 - __bfloat162float(ha23.x), a3 - __bfloat162float(ha23.y));
            uint32_t bl01 = pack_bf2(b0 - __bfloat162float(hb01.x), b1 - __bfloat162float(hb01.y));
            uint32_t bl23 = pack_bf2(b2 - __bfloat162float(hb23.x), b3 - __bfloat162float(hb23.y));
            ((uint32_t*)dA)[0] = ah01; ((uint32_t*)dA)[1] = ah23;
            ((uint32_t*)dAl)[0] = al01; ((uint32_t*)dAl)[1] = al23;
            ((uint32_t*)dB)[0] = bh01; ((uint32_t*)dB)[1] = bh23;
            ((uint32_t*)dBl)[0] = bl01; ((uint32_t*)dBl)[1] = bl23;
        }
        __syncthreads();

        // prefetch next chunk
        if (c < DD / BK - 1) {
            int k0 = (c + 1) * BK;
            #pragma unroll
            for (int i = 0; i < 4; i++) {
                va[i] = *(const float4*)(ap[i] + k0);
                vb[i] = *(const float4*)(bp[i] + k0);
            }
        }

        // HMMA over the two k16 halves of this 32-chunk
        #pragma unroll
        for (int ks = 0; ks < 2; ks++) {
            uint32_t bhf[4][2], blf[4][2];
            #pragma unroll
            for (int nt = 0; nt < 4; nt++) {
                int boff = (wx * 32 + nt * 8 + grp) * STRA + qd * 2 + ks * 16;
                bhf[nt][0] = *(const uint32_t*)(Bh + boff);
                bhf[nt][1] = *(const uint32_t*)(Bh + boff + 8);
                blf[nt][0] = *(const uint32_t*)(Bl + boff);
                blf[nt][1] = *(const uint32_t*)(Bl + boff + 8);
            }
            #pragma unroll
            for (int mt = 0; mt < 4; mt++) {
                int aoff = (wy * 64 + mt * 16 + grp) * STRA + qd * 2 + ks * 16;
                uint32_t ahf[4], alf[4];
                ahf[0] = *(const uint32_t*)(Ah + aoff);
                ahf[1] = *(const uint32_t*)(Ah + aoff + 8 * STRA);
                ahf[2] = *(const uint32_t*)(Ah + aoff + 8);
                ahf[3] = *(const uint32_t*)(Ah + aoff + 8 * STRA + 8);
                alf[0] = *(const uint32_t*)(Al + aoff);
                alf[1] = *(const uint32_t*)(Al + aoff + 8 * STRA);
                alf[2] = *(const uint32_t*)(Al + aoff + 8);
                alf[3] = *(const uint32_t*)(Al + aoff + 8 * STRA + 8);
                #pragma unroll
                for (int nt = 0; nt < 4; nt++) {
                    mma16816(acc[mt][nt], ahf, bhf[nt]);   // hi*hi
                    mma16816(acc[mt][nt], ahf, blf[nt]);   // hi*lo
                    mma16816(acc[mt][nt], alf, bhf[nt]);   // lo*hi
                }
            }
        }
        __syncthreads();
    }

    // ---- epilogue: bias add + masked store
    #pragma unroll
    for (int mt = 0; mt < 4; mt++) {
        int rA = r0 + wy * 64 + mt * 16 + grp;
        #pragma unroll
        for (int nt = 0; nt < 4; nt++) {
            int col = c0 + wx * 32 + nt * 8 + qd * 2;
            float2 bv = *(const float2*)(bias + col);
            if (rA < nr) {
                float2 v0 = make_float2(acc[mt][nt][0] + bv.x, acc[mt][nt][1] + bv.y);
                *(float2*)(out + ((size_t)b * SS + rA) * DD + col) = v0;
            }
            if (rA + 8 < nr) {
                float2 v1 = make_float2(acc[mt][nt][2] + bv.x, acc[mt][nt][3] + bv.y);
                *(float2*)(out + ((size_t)b * SS + rA + 8) * DD + col) = v1;
            }
        }
    }
}

// ------------------------------------------------- fused pair + online softmax
__global__ __launch_bounds__(256) void pair_kernel(const float* __restrict__ E) {
    int b   = blockIdx.z;
    int pid = blockIdx.y * 8 + blockIdx.x;
    int n0  = g_cnt[b], n1 = g_cnt[BB + b];
    int i0  = blockIdx.y * 64, j0 = blockIdx.x * 64;
    int tid = threadIdx.x;
    if (i0 >= n0 || j0 >= n1) {
        if (tid == 0) {
            g_pm[b * 64 + pid] = NEG_BIG;
            g_pl[b * 64 + pid] = 0.f;
            g_pa[b * 64 + pid] = 0.f;
        }
        return;
    }
    __shared__ float Qs[16][64], Is[16][64], Ks[16][64], Js[16][64];
    __shared__ float sinvi[64], sinvj[64];
    __shared__ int   si[64], sj[64];
    if (tid < 64) {
        int r  = min(i0 + tid, n0 - 1);
        int ix = g_idx0[b * SS + r];
        si[tid] = ix; sinvi[tid] = g_invn[b * SS + ix];
        int c  = min(j0 + tid, n1 - 1);
        int jx = g_idx1[b * SS + c];
        sj[tid] = jx; sinvj[tid] = g_invn[b * SS + jx];
    }
    __syncthreads();

    float accL[4][4], accG[4][4];
    #pragma unroll
    for (int i = 0; i < 4; i++)
        #pragma unroll
        for (int j = 0; j < 4; j++) { accL[i][j] = 0.f; accG[i][j] = 0.f; }

    int row = tid >> 2;
    int kk  = (tid & 3) * 4;
    int iq  = min(i0 + row, n0 - 1);
    int jq  = min(j0 + row, n1 - 1);
    const float* qptr  = g_q + ((size_t)b * SS + iq) * DD + kk;
    const float* kptr  = g_k + ((size_t)b * SS + jq) * DD + kk;
    const float* eiptr = E + ((size_t)b * SS + si[row]) * DD + kk;
    const float* ejptr = E + ((size_t)b * SS + sj[row]) * DD + kk;
    int ty = tid >> 4, tx = tid & 15;

    for (int k0 = 0; k0 < DD; k0 += 16) {
        float4 q4 = *(const float4*)(qptr + k0);
        float4 i4 = *(const float4*)(eiptr + k0);
        float4 k4 = *(const float4*)(kptr + k0);
        float4 j4 = *(const float4*)(ejptr + k0);
        Qs[kk + 0][row] = q4.x; Qs[kk + 1][row] = q4.y; Qs[kk + 2][row] = q4.z; Qs[kk + 3][row] = q4.w;
        Is[kk + 0][row] = i4.x; Is[kk + 1][row] = i4.y; Is[kk + 2][row] = i4.z; Is[kk + 3][row] = i4.w;
        Ks[kk + 0][row] = k4.x; Ks[kk + 1][row] = k4.y; Ks[kk + 2][row] = k4.z; Ks[kk + 3][row] = k4.w;
        Js[kk + 0][row] = j4.x; Js[kk + 1][row] = j4.y; Js[kk + 2][row] = j4.z; Js[kk + 3][row] = j4.w;
        __syncthreads();
        #pragma unroll
        for (int k = 0; k < 16; k++) {
            float qa[4], ia[4], kb[4], jb[4];
            *(float4*)&qa[0] = *(const float4*)&Qs[k][ty * 4];
            *(float4*)&ia[0] = *(const float4*)&Is[k][ty * 4];
            *(float4*)&kb[0] = *(const float4*)&Ks[k][tx * 4];
            *(float4*)&jb[0] = *(const float4*)&Js[k][tx * 4];
            #pragma unroll
            for (int i = 0; i < 4; i++)
                #pragma unroll
                for (int j = 0; j < 4; j++) {
                    accL[i][j] = fmaf(qa[i], kb[j], accL[i][j]);
                    accG[i][j] = fmaf(ia[i], jb[j], accG[i][j]);
                }
        }
        __syncthreads();
    }

    int ri = ty * 4, rj = tx * 4;
    float m = NEG_BIG, l = 0.f, a = 0.f;
    #pragma unroll
    for (int i = 0; i < 4; i++)
        #pragma unroll
        for (int j = 0; j < 4; j++) {
            if (i0 + ri + i < n0 && j0 + rj + j < n1)
                m = fmaxf(m, accL[i][j]);
        }
    if (m > NEG_BIG * 0.5f) {
        #pragma unroll
        for (int i = 0; i < 4; i++)
            #pragma unroll
            for (int j = 0; j < 4; j++) {
                if (i0 + ri + i < n0 && j0 + rj + j < n1) {
                    float w  = expf(accL[i][j] - m);
                    float sc = fabsf(accG[i][j]) * sinvi[ri + i] * sinvj[rj + j];
                    l += w;
                    a += w * sc;
                }
            }
    }

    __shared__ float rm_[256], rl_[256], ra_[256];
    rm_[tid] = m; rl_[tid] = l; ra_[tid] = a;
    __syncthreads();
    for (int s = 128; s > 0; s >>= 1) {
        if (tid < s) {
            float M = rm_[tid], L = rl_[tid], A = ra_[tid];
            softmax_merge(M, L, A, rm_[tid + s], rl_[tid + s], ra_[tid + s]);
            rm_[tid] = M; rl_[tid] = L; ra_[tid] = A;
        }
        __syncthreads();
    }
    if (tid == 0) {
        g_pm[b * 64 + pid] = rm_[0];
        g_pl[b * 64 + pid] = rl_[0];
        g_pa[b * 64 + pid] = ra_[0];
    }
}

// ------------------------------------------------------------------ finalize --
__global__ void finalize(float* __restrict__ out) {
    int b = blockIdx.x;
    int t = threadIdx.x;
    __shared__ float sm[64], sl[64], sa[64];
    sm[t] = g_pm[b * 64 + t];
    sl[t] = g_pl[b * 64 + t];
    sa[t] = g_pa[b * 64 + t];
    __syncthreads();
    for (int s = 32; s > 0; s >>= 1) {
        if (t < s) {
            float M = sm[t], L = sl[t], A = sa[t];
            softmax_merge(M, L, A, sm[t + s], sl[t + s], sa[t + s]);
            sm[t] = M; sl[t] = L; sa[t] = A;
        }
        __syncthreads();
    }
    if (t == 0) out[b] = (sl[0] > 0.f) ? (sa[0] / sl[0]) : 0.f;
}

// -------------------------------------------------------------------- launch --
extern "C" void kernel_launch(void* const* d_in, const int* in_sizes, int n_in,
                              void* d_out, int out_size) {
    const float* E  = (const float*)d_in[0];
    const float* Wq = (const float*)d_in[1];
    const float* bq = (const float*)d_in[2];
    const float* Wk = (const float*)d_in[3];
    const float* bk = (const float*)d_in[4];
    const int*   am = (const int*)d_in[5];
    const int*   tt = (const int*)d_in[6];
    float* out = (float*)d_out;

    prep_masks<<<BB, 512>>>(am, tt);
    row_norms<<<NTOK, 128>>>(E);
    proj_mma<<<dim3(8, 4, 2 * BB), 256>>>(E, Wq, bq, Wk, bk);
    pair_kernel<<<dim3(8, 8, BB), 256>>>(E);
    finalize<<<BB, 64>>>(out);
}

// round 4
// speedup vs baseline: 3.2379x; 1.8633x over previous
#include <cuda_runtime.h>
#include <cuda_bf16.h>
#include <math.h>
#include <stdint.h>

#define BB 16
#define SS 512
#define DD 1024
#define NTOK (BB*SS)
#define NEG_BIG (-3.0e38f)

// ------------------------------ scratch (static device globals; no allocs) --
__device__ float g_q[(size_t)NTOK * DD];
__device__ float g_k[(size_t)NTOK * DD];
__device__ float g_invn[NTOK];
__device__ int   g_idx0[NTOK];
__device__ int   g_idx1[NTOK];
__device__ int   g_cnt[2 * BB];
__device__ float g_pm[BB * 64];
__device__ float g_pl[BB * 64];
__device__ float g_pa[BB * 64];

__device__ __forceinline__ void softmax_merge(float& m1, float& l1, float& a1,
                                              float m2, float l2, float a2) {
    float M  = fmaxf(m1, m2);
    float e1 = (l1 > 0.f) ? expf(m1 - M) : 0.f;
    float e2 = (l2 > 0.f) ? expf(m2 - M) : 0.f;
    l1 = l1 * e1 + l2 * e2;
    a1 = a1 * e1 + a2 * e2;
    m1 = M;
}

__device__ __forceinline__ uint32_t pack_bf2(float x, float y) {
    __nv_bfloat162 h = __floats2bfloat162_rn(x, y);
    return *(uint32_t*)&h;
}
__device__ __forceinline__ void mma16816(float* c, const uint32_t* a, const uint32_t* b) {
    asm volatile(
        "mma.sync.aligned.m16n8k16.row.col.f32.bf16.bf16.f32 "
        "{%0,%1,%2,%3}, {%4,%5,%6,%7}, {%8,%9}, {%0,%1,%2,%3};"
        : "+f"(c[0]), "+f"(c[1]), "+f"(c[2]), "+f"(c[3])
        : "r"(a[0]), "r"(a[1]), "r"(a[2]), "r"(a[3]), "r"(b[0]), "r"(b[1]));
}

// ---------------------------------------------------------- mask compaction --
__global__ void prep_masks(const int* __restrict__ am, const int* __restrict__ tt) {
    int b = blockIdx.x;
    int t = threadIdx.x;
    int lane = t & 31, w = t >> 5;
    int a  = am[b * SS + t];
    int ty = tt[b * SS + t];
    bool f0 = (a == 1) && (ty == 0);
    bool f1 = (a == 1) && (ty == 1);
    unsigned bal0 = __ballot_sync(0xffffffffu, f0);
    unsigned bal1 = __ballot_sync(0xffffffffu, f1);
    __shared__ int wc0[16], wc1[16], off0[16], off1[16];
    if (lane == 0) { wc0[w] = __popc(bal0); wc1[w] = __popc(bal1); }
    __syncthreads();
    if (t == 0) {
        int s0 = 0, s1 = 0;
        for (int i = 0; i < 16; i++) {
            off0[i] = s0; s0 += wc0[i];
            off1[i] = s1; s1 += wc1[i];
        }
        g_cnt[b] = s0; g_cnt[BB + b] = s1;
    }
    __syncthreads();
    if (f0) g_idx0[b * SS + off0[w] + __popc(bal0 & ((1u << lane) - 1u))] = t;
    if (f1) g_idx1[b * SS + off1[w] + __popc(bal1 & ((1u << lane) - 1u))] = t;
}

// -------------------------------------------------- row inv-norms (warp/row) --
__global__ __launch_bounds__(512) void row_norms(const float* __restrict__ E) {
    int row  = blockIdx.x * 16 + (threadIdx.x >> 5);
    int lane = threadIdx.x & 31;
    const float4* p = (const float4*)(E + (size_t)row * DD);
    float s = 0.f;
    #pragma unroll
    for (int i = 0; i < 8; i++) {
        float4 v = p[lane + i * 32];
        s += v.x * v.x + v.y * v.y + v.z * v.z + v.w * v.w;
    }
    #pragma unroll
    for (int o = 16; o > 0; o >>= 1) s += __shfl_down_sync(0xffffffffu, s, o);
    if (lane == 0) g_invn[row] = 1.f / fmaxf(sqrtf(s), 1e-12f);
}

// ---------------------------------- mma.sync bf16x3 gathered projection GEMM --
#define BK 32
#define STRA 34

__global__ __launch_bounds__(256) void proj_mma(
    const float* __restrict__ E,
    const float* __restrict__ Wq, const float* __restrict__ bq,
    const float* __restrict__ Wk, const float* __restrict__ bk)
{
    int z = blockIdx.z;
    int b = z & 15, which = z >> 4;
    int nr = g_cnt[which * BB + b];
    int r0 = blockIdx.y * 128;
    if (r0 >= nr) return;
    int c0 = blockIdx.x * 128;
    const float* __restrict__ W    = which ? Wk : Wq;
    const float* __restrict__ bias = which ? bk : bq;
    const int*   __restrict__ idx  = which ? g_idx1 : g_idx0;
    float*       __restrict__ out  = which ? g_k : g_q;

    __shared__ __align__(16) uint16_t Ah[128 * STRA];
    __shared__ __align__(16) uint16_t Al[128 * STRA];
    __shared__ __align__(16) uint16_t Bh[128 * STRA];
    __shared__ __align__(16) uint16_t Bl[128 * STRA];
    __shared__ int sidx[128];

    int t = threadIdx.x;
    if (t < 128) sidx[t] = idx[b * SS + min(r0 + t, nr - 1)];
    __syncthreads();

    int lrow = t >> 3;
    int seg  = t & 7;
    const float* Eb = E + (size_t)b * SS * DD;
    const float* ap[4];
    const float* bp[4];
    #pragma unroll
    for (int i = 0; i < 4; i++) {
        int row = lrow + i * 32;
        ap[i] = Eb + (size_t)sidx[row] * DD + seg * 4;
        bp[i] = W + (size_t)(c0 + row) * DD + seg * 4;
    }

    int wid = t >> 5, lane = t & 31;
    int wy = wid >> 2, wx = wid & 3;
    int grp = lane >> 2, qd = lane & 3;

    float acc[4][4][4];
    #pragma unroll
    for (int mt = 0; mt < 4; mt++)
        #pragma unroll
        for (int nt = 0; nt < 4; nt++)
            #pragma unroll
            for (int r = 0; r < 4; r++) acc[mt][nt][r] = 0.f;

    float4 va[4], vb[4];
    #pragma unroll
    for (int i = 0; i < 4; i++) { va[i] = *(const float4*)ap[i]; vb[i] = *(const float4*)bp[i]; }

    for (int c = 0; c < DD / BK; c++) {
        #pragma unroll
        for (int i = 0; i < 4; i++) {
            int row = lrow + i * 32;
            uint16_t* dA = Ah + row * STRA + seg * 4;
            uint16_t* dAl = Al + row * STRA + seg * 4;
            uint16_t* dB = Bh + row * STRA + seg * 4;
            uint16_t* dBl = Bl + row * STRA + seg * 4;
            float a0 = va[i].x, a1 = va[i].y, a2 = va[i].z, a3 = va[i].w;
            float b0 = vb[i].x, b1 = vb[i].y, b2 = vb[i].z, b3 = vb[i].w;
            uint32_t ah01 = pack_bf2(a0, a1), ah23 = pack_bf2(a2, a3);
            uint32_t bh01 = pack_bf2(b0, b1), bh23 = pack_bf2(b2, b3);
            __nv_bfloat162 ha01 = *(__nv_bfloat162*)&ah01, ha23 = *(__nv_bfloat162*)&ah23;
            __nv_bfloat162 hb01 = *(__nv_bfloat162*)&bh01, hb23 = *(__nv_bfloat162*)&bh23;
            uint32_t al01 = pack_bf2(a0 - __bfloat162float(ha01.x), a1 - __bfloat162float(ha01.y));
            uint32_t al23 = pack_bf2(a2 - __bfloat162float(ha23.x), a3 - __bfloat162float(ha23.y));
            uint32_t bl01 = pack_bf2(b0 - __bfloat162float(hb01.x), b1 - __bfloat162float(hb01.y));
            uint32_t bl23 = pack_bf2(b2 - __bfloat162float(hb23.x), b3 - __bfloat162float(hb23.y));
            ((uint32_t*)dA)[0] = ah01; ((uint32_t*)dA)[1] = ah23;
            ((uint32_t*)dAl)[0] = al01; ((uint32_t*)dAl)[1] = al23;
            ((uint32_t*)dB)[0] = bh01; ((uint32_t*)dB)[1] = bh23;
            ((uint32_t*)dBl)[0] = bl01; ((uint32_t*)dBl)[1] = bl23;
        }
        __syncthreads();

        if (c < DD / BK - 1) {
            int k0 = (c + 1) * BK;
            #pragma unroll
            for (int i = 0; i < 4; i++) {
                va[i] = *(const float4*)(ap[i] + k0);
                vb[i] = *(const float4*)(bp[i] + k0);
            }
        }

        #pragma unroll
        for (int ks = 0; ks < 2; ks++) {
            uint32_t bhf[4][2], blf[4][2];
            #pragma unroll
            for (int nt = 0; nt < 4; nt++) {
                int boff = (wx * 32 + nt * 8 + grp) * STRA + qd * 2 + ks * 16;
                bhf[nt][0] = *(const uint32_t*)(Bh + boff);
                bhf[nt][1] = *(const uint32_t*)(Bh + boff + 8);
                blf[nt][0] = *(const uint32_t*)(Bl + boff);
                blf[nt][1] = *(const uint32_t*)(Bl + boff + 8);
            }
            #pragma unroll
            for (int mt = 0; mt < 4; mt++) {
                int aoff = (wy * 64 + mt * 16 + grp) * STRA + qd * 2 + ks * 16;
                uint32_t ahf[4], alf[4];
                ahf[0] = *(const uint32_t*)(Ah + aoff);
                ahf[1] = *(const uint32_t*)(Ah + aoff + 8 * STRA);
                ahf[2] = *(const uint32_t*)(Ah + aoff + 8);
                ahf[3] = *(const uint32_t*)(Ah + aoff + 8 * STRA + 8);
                alf[0] = *(const uint32_t*)(Al + aoff);
                alf[1] = *(const uint32_t*)(Al + aoff + 8 * STRA);
                alf[2] = *(const uint32_t*)(Al + aoff + 8);
                alf[3] = *(const uint32_t*)(Al + aoff + 8 * STRA + 8);
                #pragma unroll
                for (int nt = 0; nt < 4; nt++) {
                    mma16816(acc[mt][nt], ahf, bhf[nt]);
                    mma16816(acc[mt][nt], ahf, blf[nt]);
                    mma16816(acc[mt][nt], alf, bhf[nt]);
                }
            }
        }
        __syncthreads();
    }

    #pragma unroll
    for (int mt = 0; mt < 4; mt++) {
        int rA = r0 + wy * 64 + mt * 16 + grp;
        #pragma unroll
        for (int nt = 0; nt < 4; nt++) {
            int col = c0 + wx * 32 + nt * 8 + qd * 2;
            float2 bv = *(const float2*)(bias + col);
            if (rA < nr) {
                float2 v0 = make_float2(acc[mt][nt][0] + bv.x, acc[mt][nt][1] + bv.y);
                *(float2*)(out + ((size_t)b * SS + rA) * DD + col) = v0;
            }
            if (rA + 8 < nr) {
                float2 v1 = make_float2(acc[mt][nt][2] + bv.x, acc[mt][nt][3] + bv.y);
                *(float2*)(out + ((size_t)b * SS + rA + 8) * DD + col) = v1;
            }
        }
    }
}

// ----------------------- mma.sync bf16x3 fused pair + online softmax kernel --
// 64x64 (i x j) tiles, 8 warps (2x4 -> warp tile 32x16), dual GEMM:
// logits = q . k, gram = e_i . e_j. Epilogue: mask, |gram|*invn_i*invn_j,
// online softmax partials per block.
#define PSTR 34

__device__ __forceinline__ void split_store(uint16_t* hB, uint16_t* lB,
                                            int row, int seg, float4 v) {
    uint32_t h01 = pack_bf2(v.x, v.y), h23 = pack_bf2(v.z, v.w);
    __nv_bfloat162 a01 = *(__nv_bfloat162*)&h01, a23 = *(__nv_bfloat162*)&h23;
    uint32_t l01 = pack_bf2(v.x - __bfloat162float(a01.x), v.y - __bfloat162float(a01.y));
    uint32_t l23 = pack_bf2(v.z - __bfloat162float(a23.x), v.w - __bfloat162float(a23.y));
    uint32_t* dh = (uint32_t*)(hB + row * PSTR + seg * 4);
    uint32_t* dl = (uint32_t*)(lB + row * PSTR + seg * 4);
    dh[0] = h01; dh[1] = h23;
    dl[0] = l01; dl[1] = l23;
}

__global__ __launch_bounds__(256) void pair_mma(const float* __restrict__ E) {
    int b   = blockIdx.z;
    int pid = blockIdx.y * 8 + blockIdx.x;
    int n0  = g_cnt[b], n1 = g_cnt[BB + b];
    int i0  = blockIdx.y * 64, j0 = blockIdx.x * 64;
    int tid = threadIdx.x;
    if (i0 >= n0 || j0 >= n1) {
        if (tid == 0) {
            g_pm[b * 64 + pid] = NEG_BIG;
            g_pl[b * 64 + pid] = 0.f;
            g_pa[b * 64 + pid] = 0.f;
        }
        return;
    }

    __shared__ __align__(16) uint16_t Qh[64 * PSTR], Ql[64 * PSTR];
    __shared__ __align__(16) uint16_t Ih[64 * PSTR], Il[64 * PSTR];
    __shared__ __align__(16) uint16_t Kh[64 * PSTR], Kl[64 * PSTR];
    __shared__ __align__(16) uint16_t Jh[64 * PSTR], Jl[64 * PSTR];
    __shared__ float sinvi[64], sinvj[64];
    __shared__ int   si[64], sj[64];

    if (tid < 64) {
        int r  = min(i0 + tid, n0 - 1);
        int ix = g_idx0[b * SS + r];
        si[tid] = ix; sinvi[tid] = g_invn[b * SS + ix];
        int c  = min(j0 + tid, n1 - 1);
        int jx = g_idx1[b * SS + c];
        sj[tid] = jx; sinvj[tid] = g_invn[b * SS + jx];
    }
    __syncthreads();

    int lrow = tid >> 3, seg = tid & 7;    // lrow 0..31, seg 0..7
    const float* Eb = E + (size_t)b * SS * DD;
    const float* qp[2]; const float* ip[2]; const float* kp[2]; const float* jp[2];
    #pragma unroll
    for (int i = 0; i < 2; i++) {
        int r = lrow + i * 32;
        qp[i] = g_q + ((size_t)b * SS + min(i0 + r, n0 - 1)) * DD + seg * 4;
        ip[i] = Eb + (size_t)si[r] * DD + seg * 4;
        kp[i] = g_k + ((size_t)b * SS + min(j0 + r, n1 - 1)) * DD + seg * 4;
        jp[i] = Eb + (size_t)sj[r] * DD + seg * 4;
    }

    int wid = tid >> 5, lane = tid & 31;
    int wy = wid >> 2, wx = wid & 3;           // wy 0..1, wx 0..3
    int grp = lane >> 2, qd = lane & 3;

    float aL[2][2][4], aG[2][2][4];
    #pragma unroll
    for (int mt = 0; mt < 2; mt++)
        #pragma unroll
        for (int nt = 0; nt < 2; nt++)
            #pragma unroll
            for (int r = 0; r < 4; r++) { aL[mt][nt][r] = 0.f; aG[mt][nt][r] = 0.f; }

    float4 vq[2], vi[2], vk[2], vj[2];
    #pragma unroll
    for (int i = 0; i < 2; i++) {
        vq[i] = *(const float4*)qp[i];
        vi[i] = *(const float4*)ip[i];
        vk[i] = *(const float4*)kp[i];
        vj[i] = *(const float4*)jp[i];
    }

    for (int c = 0; c < DD / BK; c++) {
        #pragma unroll
        for (int i = 0; i < 2; i++) {
            int row = lrow + i * 32;
            split_store(Qh, Ql, row, seg, vq[i]);
            split_store(Ih, Il, row, seg, vi[i]);
            split_store(Kh, Kl, row, seg, vk[i]);
            split_store(Jh, Jl, row, seg, vj[i]);
        }
        __syncthreads();

        if (c < DD / BK - 1) {
            int k0 = (c + 1) * BK;
            #pragma unroll
            for (int i = 0; i < 2; i++) {
                vq[i] = *(const float4*)(qp[i] + k0);
                vi[i] = *(const float4*)(ip[i] + k0);
                vk[i] = *(const float4*)(kp[i] + k0);
                vj[i] = *(const float4*)(jp[i] + k0);
            }
        }

        #pragma unroll
        for (int ks = 0; ks < 2; ks++) {
            uint32_t kbh[2][2], kbl[2][2], jbh[2][2], jbl[2][2];
            #pragma unroll
            for (int nt = 0; nt < 2; nt++) {
                int boff = (wx * 16 + nt * 8 + grp) * PSTR + qd * 2 + ks * 16;
                kbh[nt][0] = *(const uint32_t*)(Kh + boff);
                kbh[nt][1] = *(const uint32_t*)(Kh + boff + 8);
                kbl[nt][0] = *(const uint32_t*)(Kl + boff);
                kbl[nt][1] = *(const uint32_t*)(Kl + boff + 8);
                jbh[nt][0] = *(const uint32_t*)(Jh + boff);
                jbh[nt][1] = *(const uint32_t*)(Jh + boff + 8);
                jbl[nt][0] = *(const uint32_t*)(Jl + boff);
                jbl[nt][1] = *(const uint32_t*)(Jl + boff + 8);
            }
            #pragma unroll
            for (int mt = 0; mt < 2; mt++) {
                int aoff = (wy * 32 + mt * 16 + grp) * PSTR + qd * 2 + ks * 16;
                uint32_t qah[4], qal[4], iah[4], ial[4];
                qah[0] = *(const uint32_t*)(Qh + aoff);
                qah[1] = *(const uint32_t*)(Qh + aoff + 8 * PSTR);
                qah[2] = *(const uint32_t*)(Qh + aoff + 8);
                qah[3] = *(const uint32_t*)(Qh + aoff + 8 * PSTR + 8);
                qal[0] = *(const uint32_t*)(Ql + aoff);
                qal[1] = *(const uint32_t*)(Ql + aoff + 8 * PSTR);
                qal[2] = *(const uint32_t*)(Ql + aoff + 8);
                qal[3] = *(const uint32_t*)(Ql + aoff + 8 * PSTR + 8);
                iah[0] = *(const uint32_t*)(Ih + aoff);
                iah[1] = *(const uint32_t*)(Ih + aoff + 8 * PSTR);
                iah[2] = *(const uint32_t*)(Ih + aoff + 8);
                iah[3] = *(const uint32_t*)(Ih + aoff + 8 * PSTR + 8);
                ial[0] = *(const uint32_t*)(Il + aoff);
                ial[1] = *(const uint32_t*)(Il + aoff + 8 * PSTR);
                ial[2] = *(const uint32_t*)(Il + aoff + 8);
                ial[3] = *(const uint32_t*)(Il + aoff + 8 * PSTR + 8);
                #pragma unroll
                for (int nt = 0; nt < 2; nt++) {
                    mma16816(aL[mt][nt], qah, kbh[nt]);
                    mma16816(aL[mt][nt], qah, kbl[nt]);
                    mma16816(aL[mt][nt], qal, kbh[nt]);
                    mma16816(aG[mt][nt], iah, jbh[nt]);
                    mma16816(aG[mt][nt], iah, jbl[nt]);
                    mma16816(aG[mt][nt], ial, jbh[nt]);
                }
            }
        }
        __syncthreads();
    }

    // ---- epilogue: per-thread online softmax over its 16 pairs
    float m = NEG_BIG, l = 0.f, a = 0.f;
    #pragma unroll
    for (int mt = 0; mt < 2; mt++)
        #pragma unroll
        for (int nt = 0; nt < 2; nt++)
            #pragma unroll
            for (int rr = 0; rr < 2; rr++)
                #pragma unroll
                for (int cc = 0; cc < 2; cc++) {
                    int li = wy * 32 + mt * 16 + grp + rr * 8;
                    int lj = wx * 16 + nt * 8 + qd * 2 + cc;
                    if (i0 + li < n0 && j0 + lj < n1)
                        m = fmaxf(m, aL[mt][nt][rr * 2 + cc]);
                }
    if (m > NEG_BIG * 0.5f) {
        #pragma unroll
        for (int mt = 0; mt < 2; mt++)
            #pragma unroll
            for (int nt = 0; nt < 2; nt++)
                #pragma unroll
                for (int rr = 0; rr < 2; rr++)
                    #pragma unroll
                    for (int cc = 0; cc < 2; cc++) {
                        int li = wy * 32 + mt * 16 + grp + rr * 8;
                        int lj = wx * 16 + nt * 8 + qd * 2 + cc;
                        if (i0 + li < n0 && j0 + lj < n1) {
                            float w  = expf(aL[mt][nt][rr * 2 + cc] - m);
                            float sc = fabsf(aG[mt][nt][rr * 2 + cc]) * sinvi[li] * sinvj[lj];
                            l += w;
                            a += w * sc;
                        }
                    }
    }

    __shared__ float rm_[256], rl_[256], ra_[256];
    rm_[tid] = m; rl_[tid] = l; ra_[tid] = a;
    __syncthreads();
    for (int s = 128; s > 0; s >>= 1) {
        if (tid < s) {
            float M = rm_[tid], L = rl_[tid], A = ra_[tid];
            softmax_merge(M, L, A, rm_[tid + s], rl_[tid + s], ra_[tid + s]);
            rm_[tid] = M; rl_[tid] = L; ra_[tid] = A;
        }
        __syncthreads();
    }
    if (tid == 0) {
        g_pm[b * 64 + pid] = rm_[0];
        g_pl[b * 64 + pid] = rl_[0];
        g_pa[b * 64 + pid] = ra_[0];
    }
}

// ------------------------------------------------------------------ finalize --
__global__ void finalize(float* __restrict__ out) {
    int b = blockIdx.x;
    int t = threadIdx.x;
    __shared__ float sm[64], sl[64], sa[64];
    sm[t] = g_pm[b * 64 + t];
    sl[t] = g_pl[b * 64 + t];
    sa[t] = g_pa[b * 64 + t];
    __syncthreads();
    for (int s = 32; s > 0; s >>= 1) {
        if (t < s) {
            float M = sm[t], L = sl[t], A = sa[t];
            softmax_merge(M, L, A, sm[t + s], sl[t + s], sa[t + s]);
            sm[t] = M; sl[t] = L; sa[t] = A;
        }
        __syncthreads();
    }
    if (t == 0) out[b] = (sl[0] > 0.f) ? (sa[0] / sl[0]) : 0.f;
}

// -------------------------------------------------------------------- launch --
extern "C" void kernel_launch(void* const* d_in, const int* in_sizes, int n_in,
                              void* d_out, int out_size) {
    const float* E  = (const float*)d_in[0];
    const float* Wq = (const float*)d_in[1];
    const float* bq = (const float*)d_in[2];
    const float* Wk = (const float*)d_in[3];
    const float* bk = (const float*)d_in[4];
    const int*   am = (const int*)d_in[5];
    const int*   tt = (const int*)d_in[6];
    float* out = (float*)d_out;

    prep_masks<<<BB, 512>>>(am, tt);
    row_norms<<<NTOK / 16, 512>>>(E);
    proj_mma<<<dim3(8, 4, 2 * BB), 256>>>(E, Wq, bq, Wk, bk);
    pair_mma<<<dim3(8, 8, BB), 256>>>(E);
    finalize<<<BB, 64>>>(out);
}

// round 5
// speedup vs baseline: 3.3329x; 1.0293x over previous
#include <cuda_runtime.h>
#include <cuda_bf16.h>
#include <math.h>
#include <stdint.h>

#define BB 16
#define SS 512
#define DD 1024
#define NTOK (BB*SS)
#define NEG_BIG (-3.0e38f)
#define NPID 256            // pair partials per batch (16x16 tiles of 32)

// ------------------------------ scratch (static device globals; no allocs) --
__device__ float g_q[(size_t)NTOK * DD];
__device__ float g_k[(size_t)NTOK * DD];
__device__ float g_invn[NTOK];
__device__ int   g_idx0[NTOK];
__device__ int   g_idx1[NTOK];
__device__ int   g_cnt[2 * BB];
__device__ float g_pm[BB * NPID];
__device__ float g_pl[BB * NPID];
__device__ float g_pa[BB * NPID];

__device__ __forceinline__ void softmax_merge(float& m1, float& l1, float& a1,
                                              float m2, float l2, float a2) {
    float M  = fmaxf(m1, m2);
    float e1 = (l1 > 0.f) ? expf(m1 - M) : 0.f;
    float e2 = (l2 > 0.f) ? expf(m2 - M) : 0.f;
    l1 = l1 * e1 + l2 * e2;
    a1 = a1 * e1 + a2 * e2;
    m1 = M;
}

__device__ __forceinline__ uint32_t pack_bf2(float x, float y) {
    __nv_bfloat162 h = __floats2bfloat162_rn(x, y);
    return *(uint32_t*)&h;
}
__device__ __forceinline__ void mma16816(float* c, const uint32_t* a, const uint32_t* b) {
    asm volatile(
        "mma.sync.aligned.m16n8k16.row.col.f32.bf16.bf16.f32 "
        "{%0,%1,%2,%3}, {%4,%5,%6,%7}, {%8,%9}, {%0,%1,%2,%3};"
        : "+f"(c[0]), "+f"(c[1]), "+f"(c[2]), "+f"(c[3])
        : "r"(a[0]), "r"(a[1]), "r"(a[2]), "r"(a[3]), "r"(b[0]), "r"(b[1]));
}

// ---------------------------------------------------------- mask compaction --
__global__ void prep_masks(const int* __restrict__ am, const int* __restrict__ tt) {
    int b = blockIdx.x;
    int t = threadIdx.x;
    int lane = t & 31, w = t >> 5;
    int a  = am[b * SS + t];
    int ty = tt[b * SS + t];
    bool f0 = (a == 1) && (ty == 0);
    bool f1 = (a == 1) && (ty == 1);
    unsigned bal0 = __ballot_sync(0xffffffffu, f0);
    unsigned bal1 = __ballot_sync(0xffffffffu, f1);
    __shared__ int wc0[16], wc1[16], off0[16], off1[16];
    if (lane == 0) { wc0[w] = __popc(bal0); wc1[w] = __popc(bal1); }
    __syncthreads();
    if (t == 0) {
        int s0 = 0, s1 = 0;
        for (int i = 0; i < 16; i++) {
            off0[i] = s0; s0 += wc0[i];
            off1[i] = s1; s1 += wc1[i];
        }
        g_cnt[b] = s0; g_cnt[BB + b] = s1;
    }
    __syncthreads();
    if (f0) g_idx0[b * SS + off0[w] + __popc(bal0 & ((1u << lane) - 1u))] = t;
    if (f1) g_idx1[b * SS + off1[w] + __popc(bal1 & ((1u << lane) - 1u))] = t;
}

// -------------------------------------------------- row inv-norms (warp/row) --
__global__ __launch_bounds__(512) void row_norms(const float* __restrict__ E) {
    int row  = blockIdx.x * 16 + (threadIdx.x >> 5);
    int lane = threadIdx.x & 31;
    const float4* p = (const float4*)(E + (size_t)row * DD);
    float s = 0.f;
    #pragma unroll
    for (int i = 0; i < 8; i++) {
        float4 v = p[lane + i * 32];
        s += v.x * v.x + v.y * v.y + v.z * v.z + v.w * v.w;
    }
    #pragma unroll
    for (int o = 16; o > 0; o >>= 1) s += __shfl_down_sync(0xffffffffu, s, o);
    if (lane == 0) g_invn[row] = 1.f / fmaxf(sqrtf(s), 1e-12f);
}

// ------------------ mma.sync bf16x3 gathered projection GEMM (64-row tiles) --
#define BK 32
#define STRA 34

__global__ __launch_bounds__(256) void proj_mma(
    const float* __restrict__ E,
    const float* __restrict__ Wq, const float* __restrict__ bq,
    const float* __restrict__ Wk, const float* __restrict__ bk)
{
    int z = blockIdx.z;
    int b = z & 15, which = z >> 4;
    int nr = g_cnt[which * BB + b];
    int r0 = blockIdx.y * 64;
    if (r0 >= nr) return;
    int c0 = blockIdx.x * 128;
    const float* __restrict__ W    = which ? Wk : Wq;
    const float* __restrict__ bias = which ? bk : bq;
    const int*   __restrict__ idx  = which ? g_idx1 : g_idx0;
    float*       __restrict__ out  = which ? g_k : g_q;

    __shared__ __align__(16) uint16_t Ah[64 * STRA];
    __shared__ __align__(16) uint16_t Al[64 * STRA];
    __shared__ __align__(16) uint16_t Bh[128 * STRA];
    __shared__ __align__(16) uint16_t Bl[128 * STRA];
    __shared__ int sidx[64];

    int t = threadIdx.x;
    if (t < 64) sidx[t] = idx[b * SS + min(r0 + t, nr - 1)];
    __syncthreads();

    int lrow = t >> 3;            // 0..31
    int seg  = t & 7;             // 0..7
    const float* Eb = E + (size_t)b * SS * DD;
    const float* ap[2];
    const float* bp[4];
    #pragma unroll
    for (int i = 0; i < 2; i++)
        ap[i] = Eb + (size_t)sidx[lrow + i * 32] * DD + seg * 4;
    #pragma unroll
    for (int i = 0; i < 4; i++)
        bp[i] = W + (size_t)(c0 + lrow + i * 32) * DD + seg * 4;

    int wid = t >> 5, lane = t & 31;
    int wy = wid >> 2, wx = wid & 3;        // wy 0..1 (32-row band), wx 0..3
    int grp = lane >> 2, qd = lane & 3;

    float acc[2][4][4];
    #pragma unroll
    for (int mt = 0; mt < 2; mt++)
        #pragma unroll
        for (int nt = 0; nt < 4; nt++)
            #pragma unroll
            for (int r = 0; r < 4; r++) acc[mt][nt][r] = 0.f;

    float4 va[2], vb[4];
    #pragma unroll
    for (int i = 0; i < 2; i++) va[i] = *(const float4*)ap[i];
    #pragma unroll
    for (int i = 0; i < 4; i++) vb[i] = *(const float4*)bp[i];

    for (int c = 0; c < DD / BK; c++) {
        #pragma unroll
        for (int i = 0; i < 2; i++) {
            int row = lrow + i * 32;
            float a0 = va[i].x, a1 = va[i].y, a2 = va[i].z, a3 = va[i].w;
            uint32_t h01 = pack_bf2(a0, a1), h23 = pack_bf2(a2, a3);
            __nv_bfloat162 s01 = *(__nv_bfloat162*)&h01, s23 = *(__nv_bfloat162*)&h23;
            uint32_t l01 = pack_bf2(a0 - __bfloat162float(s01.x), a1 - __bfloat162float(s01.y));
            uint32_t l23 = pack_bf2(a2 - __bfloat162float(s23.x), a3 - __bfloat162float(s23.y));
            uint32_t* dh = (uint32_t*)(Ah + row * STRA + seg * 4);
            uint32_t* dl = (uint32_t*)(Al + row * STRA + seg * 4);
            dh[0] = h01; dh[1] = h23; dl[0] = l01; dl[1] = l23;
        }
        #pragma unroll
        for (int i = 0; i < 4; i++) {
            int row = lrow + i * 32;
            float b0 = vb[i].x, b1 = vb[i].y, b2 = vb[i].z, b3 = vb[i].w;
            uint32_t h01 = pack_bf2(b0, b1), h23 = pack_bf2(b2, b3);
            __nv_bfloat162 s01 = *(__nv_bfloat162*)&h01, s23 = *(__nv_bfloat162*)&h23;
            uint32_t l01 = pack_bf2(b0 - __bfloat162float(s01.x), b1 - __bfloat162float(s01.y));
            uint32_t l23 = pack_bf2(b2 - __bfloat162float(s23.x), b3 - __bfloat162float(s23.y));
            uint32_t* dh = (uint32_t*)(Bh + row * STRA + seg * 4);
            uint32_t* dl = (uint32_t*)(Bl + row * STRA + seg * 4);
            dh[0] = h01; dh[1] = h23; dl[0] = l01; dl[1] = l23;
        }
        __syncthreads();

        if (c < DD / BK - 1) {
            int k0 = (c + 1) * BK;
            #pragma unroll
            for (int i = 0; i < 2; i++) va[i] = *(const float4*)(ap[i] + k0);
            #pragma unroll
            for (int i = 0; i < 4; i++) vb[i] = *(const float4*)(bp[i] + k0);
        }

        #pragma unroll
        for (int ks = 0; ks < 2; ks++) {
            uint32_t bhf[4][2], blf[4][2];
            #pragma unroll
            for (int nt = 0; nt < 4; nt++) {
                int boff = (wx * 32 + nt * 8 + grp) * STRA + qd * 2 + ks * 16;
                bhf[nt][0] = *(const uint32_t*)(Bh + boff);
                bhf[nt][1] = *(const uint32_t*)(Bh + boff + 8);
                blf[nt][0] = *(const uint32_t*)(Bl + boff);
                blf[nt][1] = *(const uint32_t*)(Bl + boff + 8);
            }
            #pragma unroll
            for (int mt = 0; mt < 2; mt++) {
                int aoff = (wy * 32 + mt * 16 + grp) * STRA + qd * 2 + ks * 16;
                uint32_t ahf[4], alf[4];
                ahf[0] = *(const uint32_t*)(Ah + aoff);
                ahf[1] = *(const uint32_t*)(Ah + aoff + 8 * STRA);
                ahf[2] = *(const uint32_t*)(Ah + aoff + 8);
                ahf[3] = *(const uint32_t*)(Ah + aoff + 8 * STRA + 8);
                alf[0] = *(const uint32_t*)(Al + aoff);
                alf[1] = *(const uint32_t*)(Al + aoff + 8 * STRA);
                alf[2] = *(const uint32_t*)(Al + aoff + 8);
                alf[3] = *(const uint32_t*)(Al + aoff + 8 * STRA + 8);
                #pragma unroll
                for (int nt = 0; nt < 4; nt++) {
                    mma16816(acc[mt][nt], ahf, bhf[nt]);
                    mma16816(acc[mt][nt], ahf, blf[nt]);
                    mma16816(acc[mt][nt], alf, bhf[nt]);
                }
            }
        }
        __syncthreads();
    }

    #pragma unroll
    for (int mt = 0; mt < 2; mt++) {
        int rA = r0 + wy * 32 + mt * 16 + grp;
        #pragma unroll
        for (int nt = 0; nt < 4; nt++) {
            int col = c0 + wx * 32 + nt * 8 + qd * 2;
            float2 bv = *(const float2*)(bias + col);
            if (rA < nr) {
                float2 v0 = make_float2(acc[mt][nt][0] + bv.x, acc[mt][nt][1] + bv.y);
                *(float2*)(out + ((size_t)b * SS + rA) * DD + col) = v0;
            }
            if (rA + 8 < nr) {
                float2 v1 = make_float2(acc[mt][nt][2] + bv.x, acc[mt][nt][3] + bv.y);
                *(float2*)(out + ((size_t)b * SS + rA + 8) * DD + col) = v1;
            }
        }
    }
}

// --------------- mma.sync bf16x3 fused pair + online softmax (32x32 tiles) --
#define PSTR 34

__device__ __forceinline__ void split_store(uint16_t* hB, uint16_t* lB,
                                            int row, int seg, float4 v) {
    uint32_t h01 = pack_bf2(v.x, v.y), h23 = pack_bf2(v.z, v.w);
    __nv_bfloat162 a01 = *(__nv_bfloat162*)&h01, a23 = *(__nv_bfloat162*)&h23;
    uint32_t l01 = pack_bf2(v.x - __bfloat162float(a01.x), v.y - __bfloat162float(a01.y));
    uint32_t l23 = pack_bf2(v.z - __bfloat162float(a23.x), v.w - __bfloat162float(a23.y));
    uint32_t* dh = (uint32_t*)(hB + row * PSTR + seg * 4);
    uint32_t* dl = (uint32_t*)(lB + row * PSTR + seg * 4);
    dh[0] = h01; dh[1] = h23;
    dl[0] = l01; dl[1] = l23;
}

__global__ __launch_bounds__(128) void pair_mma(const float* __restrict__ E) {
    int b   = blockIdx.z;
    int pid = blockIdx.y * 16 + blockIdx.x;
    int n0  = g_cnt[b], n1 = g_cnt[BB + b];
    int i0  = blockIdx.y * 32, j0 = blockIdx.x * 32;
    int tid = threadIdx.x;
    if (i0 >= n0 || j0 >= n1) {
        if (tid == 0) {
            g_pm[b * NPID + pid] = NEG_BIG;
            g_pl[b * NPID + pid] = 0.f;
            g_pa[b * NPID + pid] = 0.f;
        }
        return;
    }

    __shared__ __align__(16) uint16_t Qh[32 * PSTR], Ql[32 * PSTR];
    __shared__ __align__(16) uint16_t Ih[32 * PSTR], Il[32 * PSTR];
    __shared__ __align__(16) uint16_t Kh[32 * PSTR], Kl[32 * PSTR];
    __shared__ __align__(16) uint16_t Jh[32 * PSTR], Jl[32 * PSTR];
    __shared__ float sinvi[32], sinvj[32];
    __shared__ int   si[32], sj[32];

    if (tid < 32) {
        int r  = min(i0 + tid, n0 - 1);
        int ix = g_idx0[b * SS + r];
        si[tid] = ix; sinvi[tid] = g_invn[b * SS + ix];
        int c  = min(j0 + tid, n1 - 1);
        int jx = g_idx1[b * SS + c];
        sj[tid] = jx; sinvj[tid] = g_invn[b * SS + jx];
    }
    __syncthreads();

    int lrow = tid >> 3, seg = tid & 7;    // lrow 0..15, seg 0..7
    const float* Eb = E + (size_t)b * SS * DD;
    const float* qp[2]; const float* ip[2]; const float* kp[2]; const float* jp[2];
    #pragma unroll
    for (int i = 0; i < 2; i++) {
        int r = lrow + i * 16;
        qp[i] = g_q + ((size_t)b * SS + min(i0 + r, n0 - 1)) * DD + seg * 4;
        ip[i] = Eb + (size_t)si[r] * DD + seg * 4;
        kp[i] = g_k + ((size_t)b * SS + min(j0 + r, n1 - 1)) * DD + seg * 4;
        jp[i] = Eb + (size_t)sj[r] * DD + seg * 4;
    }

    int wid = tid >> 5, lane = tid & 31;
    int wy = wid >> 1, wx = wid & 1;           // 2x2 warps, warp tile 16x16
    int grp = lane >> 2, qd = lane & 3;

    float aL[2][4], aG[2][4];
    #pragma unroll
    for (int nt = 0; nt < 2; nt++)
        #pragma unroll
        for (int r = 0; r < 4; r++) { aL[nt][r] = 0.f; aG[nt][r] = 0.f; }

    float4 vq[2], vi[2], vk[2], vj[2];
    #pragma unroll
    for (int i = 0; i < 2; i++) {
        vq[i] = *(const float4*)qp[i];
        vi[i] = *(const float4*)ip[i];
        vk[i] = *(const float4*)kp[i];
        vj[i] = *(const float4*)jp[i];
    }

    for (int c = 0; c < DD / BK; c++) {
        #pragma unroll
        for (int i = 0; i < 2; i++) {
            int row = lrow + i * 16;
            split_store(Qh, Ql, row, seg, vq[i]);
            split_store(Ih, Il, row, seg, vi[i]);
            split_store(Kh, Kl, row, seg, vk[i]);
            split_store(Jh, Jl, row, seg, vj[i]);
        }
        __syncthreads();

        if (c < DD / BK - 1) {
            int k0 = (c + 1) * BK;
            #pragma unroll
            for (int i = 0; i < 2; i++) {
                vq[i] = *(const float4*)(qp[i] + k0);
                vi[i] = *(const float4*)(ip[i] + k0);
                vk[i] = *(const float4*)(kp[i] + k0);
                vj[i] = *(const float4*)(jp[i] + k0);
            }
        }

        #pragma unroll
        for (int ks = 0; ks < 2; ks++) {
            uint32_t kbh[2][2], kbl[2][2], jbh[2][2], jbl[2][2];
            #pragma unroll
            for (int nt = 0; nt < 2; nt++) {
                int boff = (wx * 16 + nt * 8 + grp) * PSTR + qd * 2 + ks * 16;
                kbh[nt][0] = *(const uint32_t*)(Kh + boff);
                kbh[nt][1] = *(const uint32_t*)(Kh + boff + 8);
                kbl[nt][0] = *(const uint32_t*)(Kl + boff);
                kbl[nt][1] = *(const uint32_t*)(Kl + boff + 8);
                jbh[nt][0] = *(const uint32_t*)(Jh + boff);
                jbh[nt][1] = *(const uint32_t*)(Jh + boff + 8);
                jbl[nt][0] = *(const uint32_t*)(Jl + boff);
                jbl[nt][1] = *(const uint32_t*)(Jl + boff + 8);
            }
            int aoff = (wy * 16 + grp) * PSTR + qd * 2 + ks * 16;
            uint32_t qah[4], qal[4], iah[4], ial[4];
            qah[0] = *(const uint32_t*)(Qh + aoff);
            qah[1] = *(const uint32_t*)(Qh + aoff + 8 * PSTR);
            qah[2] = *(const uint32_t*)(Qh + aoff + 8);
            qah[3] = *(const uint32_t*)(Qh + aoff + 8 * PSTR + 8);
            qal[0] = *(const uint32_t*)(Ql + aoff);
            qal[1] = *(const uint32_t*)(Ql + aoff + 8 * PSTR);
            qal[2] = *(const uint32_t*)(Ql + aoff + 8);
            qal[3] = *(const uint32_t*)(Ql + aoff + 8 * PSTR + 8);
            iah[0] = *(const uint32_t*)(Ih + aoff);
            iah[1] = *(const uint32_t*)(Ih + aoff + 8 * PSTR);
            iah[2] = *(const uint32_t*)(Ih + aoff + 8);
            iah[3] = *(const uint32_t*)(Ih + aoff + 8 * PSTR + 8);
            ial[0] = *(const uint32_t*)(Il + aoff);
            ial[1] = *(const uint32_t*)(Il + aoff + 8 * PSTR);
            ial[2] = *(const uint32_t*)(Il + aoff + 8);
            ial[3] = *(const uint32_t*)(Il + aoff + 8 * PSTR + 8);
            #pragma unroll
            for (int nt = 0; nt < 2; nt++) {
                mma16816(aL[nt], qah, kbh[nt]);
                mma16816(aL[nt], qah, kbl[nt]);
                mma16816(aL[nt], qal, kbh[nt]);
                mma16816(aG[nt], iah, jbh[nt]);
                mma16816(aG[nt], iah, jbl[nt]);
                mma16816(aG[nt], ial, jbh[nt]);
            }
        }
        __syncthreads();
    }

    // ---- epilogue: per-thread online softmax over its 8 pairs
    float m = NEG_BIG, l = 0.f, a = 0.f;
    #pragma unroll
    for (int nt = 0; nt < 2; nt++)
        #pragma unroll
        for (int rr = 0; rr < 2; rr++)
            #pragma unroll
            for (int cc = 0; cc < 2; cc++) {
                int li = wy * 16 + grp + rr * 8;
                int lj = wx * 16 + nt * 8 + qd * 2 + cc;
                if (i0 + li < n0 && j0 + lj < n1)
                    m = fmaxf(m, aL[nt][rr * 2 + cc]);
            }
    if (m > NEG_BIG * 0.5f) {
        #pragma unroll
        for (int nt = 0; nt < 2; nt++)
            #pragma unroll
            for (int rr = 0; rr < 2; rr++)
                #pragma unroll
                for (int cc = 0; cc < 2; cc++) {
                    int li = wy * 16 + grp + rr * 8;
                    int lj = wx * 16 + nt * 8 + qd * 2 + cc;
                    if (i0 + li < n0 && j0 + lj < n1) {
                        float w  = expf(aL[nt][rr * 2 + cc] - m);
                        float sc = fabsf(aG[nt][rr * 2 + cc]) * sinvi[li] * sinvj[lj];
                        l += w;
                        a += w * sc;
                    }
                }
    }

    __shared__ float rm_[128], rl_[128], ra_[128];
    rm_[tid] = m; rl_[tid] = l; ra_[tid] = a;
    __syncthreads();
    for (int s = 64; s > 0; s >>= 1) {
        if (tid < s) {
            float M = rm_[tid], L = rl_[tid], A = ra_[tid];
            softmax_merge(M, L, A, rm_[tid + s], rl_[tid + s], ra_[tid + s]);
            rm_[tid] = M; rl_[tid] = L; ra_[tid] = A;
        }
        __syncthreads();
    }
    if (tid == 0) {
        g_pm[b * NPID + pid] = rm_[0];
        g_pl[b * NPID + pid] = rl_[0];
        g_pa[b * NPID + pid] = ra_[0];
    }
}

// ------------------------------------------------------------------ finalize --
__global__ __launch_bounds__(256) void finalize(float* __restrict__ out) {
    int b = blockIdx.x;
    int t = threadIdx.x;   // 256 threads = NPID partials
    __shared__ float sm[256], sl[256], sa[256];
    sm[t] = g_pm[b * NPID + t];
    sl[t] = g_pl[b * NPID + t];
    sa[t] = g_pa[b * NPID + t];
    __syncthreads();
    for (int s = 128; s > 0; s >>= 1) {
        if (t < s) {
            float M = sm[t], L = sl[t], A = sa[t];
            softmax_merge(M, L, A, sm[t + s], sl[t + s], sa[t + s]);
            sm[t] = M; sl[t] = L; sa[t] = A;
        }
        __syncthreads();
    }
    if (t == 0) out[b] = (sl[0] > 0.f) ? (sa[0] / sl[0]) : 0.f;
}

// -------------------------------------------------------------------- launch --
extern "C" void kernel_launch(void* const* d_in, const int* in_sizes, int n_in,
                              void* d_out, int out_size) {
    const float* E  = (const float*)d_in[0];
    const float* Wq = (const float*)d_in[1];
    const float* bq = (const float*)d_in[2];
    const float* Wk = (const float*)d_in[3];
    const float* bk = (const float*)d_in[4];
    const int*   am = (const int*)d_in[5];
    const int*   tt = (const int*)d_in[6];
    float* out = (float*)d_out;

    prep_masks<<<BB, 512>>>(am, tt);
    row_norms<<<NTOK / 16, 512>>>(E);
    proj_mma<<<dim3(8, 8, 2 * BB), 256>>>(E, Wq, bq, Wk, bk);
    pair_mma<<<dim3(16, 16, BB), 128>>>(E);
    finalize<<<BB, 256>>>(out);
}